// round 8
// baseline (speedup 1.0000x reference)
#include <cuda_runtime.h>

typedef unsigned long long u64;

#define NB 256
#define NNODES 511
#define HD 256

// ---------------- scratch (device globals; no allocation allowed) ----------
__device__ float g_h [NB * NNODES * HD];   // h for every tree node
__device__ float g_c [NB * NNODES * HD];   // c for every tree node
__device__ float g_ht[NB * 128 * HD];      // h_tild for current level (max m=128)
__device__ float g_ca[NB * 128 * HD];      // c_agg  for current level
__device__ float g_x2[NB * 544];           // [head_h | inner_mean | emo]

// ---------------- helpers --------------------------------------------------
__device__ __forceinline__ float sigf(float x) { return 1.0f / (1.0f + __expf(-x)); }
__device__ __forceinline__ float tanh_f(float x) { return 2.0f / (1.0f + __expf(-2.0f * x)) - 1.0f; }

__device__ __forceinline__ u64 pk2(float x, float y) {
    u64 r;
    asm("mov.b64 %0, {%1, %2};" : "=l"(r)
        : "r"(__float_as_uint(x)), "r"(__float_as_uint(y)));
    return r;
}
__device__ __forceinline__ u64 fma2(u64 a, u64 b, u64 c) {
    u64 d;
    asm("fma.rn.f32x2 %0, %1, %2, %3;" : "=l"(d) : "l"(a), "l"(b), "l"(c));
    return d;
}
__device__ __forceinline__ void upk2(u64 v, float& x, float& y) {
    unsigned a, b;
    asm("mov.b64 {%0, %1}, %2;" : "=r"(a), "=r"(b) : "l"(v));
    x = __uint_as_float(a);
    y = __uint_as_float(b);
}

// ---------------------------------------------------------------------------
// iou_kernel: C = A @ W^T for W in R^{768x256}, fused LSTM gate epilogue.
// 64 rows x 64 h-cols per block; i/o/u computed together (cols n, n+256, n+512)
// so the cell update (c = i*u + c_agg; h = o*tanh(c)) fuses in-register.
// A tile stored k-major in smem (one LDS.128 broadcast per kk); 2-stage
// double buffering hides the global loads behind the FFMA2 stream.
// ---------------------------------------------------------------------------
__global__ __launch_bounds__(256)
void iou_kernel(const float* __restrict__ A, const float* __restrict__ W,
                const float* __restrict__ bi, const float* __restrict__ Cin,
                int m, int mshift, int leaf)
{
    __shared__ __align__(16) float As[2][16][68];    // [buf][k][row]
    __shared__ __align__(16) float Ws[2][16][196];   // [buf][k][gate*64+col]

    const int tid  = threadIdx.x;
    const int h0   = blockIdx.x * 64;   // h-col tile (0..3)
    const int row0 = blockIdx.y * 64;   // row tile

    // ---- A-load mapping: 4 threads per row, one float4 each per k-tile
    const int arow = tid >> 2;
    const int kq   = (tid & 3) << 2;
    const int rA    = row0 + arow;
    const int bA    = rA >> mshift;
    const int jA    = rA & (m - 1);
    const int growA = bA * 511 + (m - 1) + jA;
    const float* aptr = (leaf ? (A + growA * 256) : (g_ht + rA * 256)) + kq;

    // ---- W-load mapping: each thread loads (col nl, k kq..kq+3) for 3 gates
    const int nl = tid >> 2;             // 0..63: col within tile
    const float* wptr0 = W + (      h0 + nl) * 256 + kq;
    const float* wptr1 = W + (256 + h0 + nl) * 256 + kq;
    const float* wptr2 = W + (512 + h0 + nl) * 256 + kq;

    const int tr = tid >> 4;
    const int tc = tid & 15;
    const int rb = tr << 2;
    const int cb = tc << 2;

    u64 acc[3][4][2];
#pragma unroll
    for (int g = 0; g < 3; ++g)
#pragma unroll
        for (int i = 0; i < 4; ++i) { acc[g][i][0] = 0ull; acc[g][i][1] = 0ull; }

    // ---- prologue: load tile 0 into buffer 0
    float4 ra  = *(const float4*)(aptr);
    float4 rw0 = *(const float4*)(wptr0);
    float4 rw1 = *(const float4*)(wptr1);
    float4 rw2 = *(const float4*)(wptr2);
    As[0][kq + 0][arow] = ra.x;  As[0][kq + 1][arow] = ra.y;
    As[0][kq + 2][arow] = ra.z;  As[0][kq + 3][arow] = ra.w;
    Ws[0][kq + 0][nl]       = rw0.x; Ws[0][kq + 1][nl]       = rw0.y;
    Ws[0][kq + 2][nl]       = rw0.z; Ws[0][kq + 3][nl]       = rw0.w;
    Ws[0][kq + 0][64 + nl]  = rw1.x; Ws[0][kq + 1][64 + nl]  = rw1.y;
    Ws[0][kq + 2][64 + nl]  = rw1.z; Ws[0][kq + 3][64 + nl]  = rw1.w;
    Ws[0][kq + 0][128 + nl] = rw2.x; Ws[0][kq + 1][128 + nl] = rw2.y;
    Ws[0][kq + 2][128 + nl] = rw2.z; Ws[0][kq + 3][128 + nl] = rw2.w;
    __syncthreads();

#pragma unroll 1
    for (int kt = 0; kt < 16; ++kt) {
        const int cur = kt & 1;
        const int nxt = cur ^ 1;
        if (kt < 15) {
            const int k0 = (kt + 1) << 4;
            ra  = *(const float4*)(aptr + k0);
            rw0 = *(const float4*)(wptr0 + k0);
            rw1 = *(const float4*)(wptr1 + k0);
            rw2 = *(const float4*)(wptr2 + k0);
        }

        const float (*Asb)[68]  = As[cur];
        const float (*Wsb)[196] = Ws[cur];
#pragma unroll
        for (int kk = 0; kk < 16; ++kk) {
            float4 a4 = *(const float4*)&Asb[kk][rb];
            u64 p0 = pk2(a4.x, a4.x), p1 = pk2(a4.y, a4.y);
            u64 p2 = pk2(a4.z, a4.z), p3 = pk2(a4.w, a4.w);
#pragma unroll
            for (int g = 0; g < 3; ++g) {
                ulonglong2 w = *(const ulonglong2*)&Wsb[kk][g * 64 + cb];
                acc[g][0][0] = fma2(p0, w.x, acc[g][0][0]);
                acc[g][0][1] = fma2(p0, w.y, acc[g][0][1]);
                acc[g][1][0] = fma2(p1, w.x, acc[g][1][0]);
                acc[g][1][1] = fma2(p1, w.y, acc[g][1][1]);
                acc[g][2][0] = fma2(p2, w.x, acc[g][2][0]);
                acc[g][2][1] = fma2(p2, w.y, acc[g][2][1]);
                acc[g][3][0] = fma2(p3, w.x, acc[g][3][0]);
                acc[g][3][1] = fma2(p3, w.y, acc[g][3][1]);
            }
        }

        if (kt < 15) {
            As[nxt][kq + 0][arow] = ra.x;  As[nxt][kq + 1][arow] = ra.y;
            As[nxt][kq + 2][arow] = ra.z;  As[nxt][kq + 3][arow] = ra.w;
            Ws[nxt][kq + 0][nl]       = rw0.x; Ws[nxt][kq + 1][nl]       = rw0.y;
            Ws[nxt][kq + 2][nl]       = rw0.z; Ws[nxt][kq + 3][nl]       = rw0.w;
            Ws[nxt][kq + 0][64 + nl]  = rw1.x; Ws[nxt][kq + 1][64 + nl]  = rw1.y;
            Ws[nxt][kq + 2][64 + nl]  = rw1.z; Ws[nxt][kq + 3][64 + nl]  = rw1.w;
            Ws[nxt][kq + 0][128 + nl] = rw2.x; Ws[nxt][kq + 1][128 + nl] = rw2.y;
            Ws[nxt][kq + 2][128 + nl] = rw2.z; Ws[nxt][kq + 3][128 + nl] = rw2.w;
            __syncthreads();
        }
    }

    // ---- epilogue: gates + cell update + store h,c ----
#pragma unroll
    for (int i = 0; i < 4; ++i) {
        const int r    = row0 + rb + i;
        const int b    = r >> mshift;
        const int j    = r & (m - 1);
        const int grow = b * 511 + (m - 1) + j;
        const int col  = h0 + cb;

        float4 ca4 = leaf ? *(const float4*)(Cin + grow * 256 + col)
                          : *(const float4*)(g_ca + r * 256 + col);
        float caA[4] = {ca4.x, ca4.y, ca4.z, ca4.w};

        float vi[4], vo[4], vu[4];
        upk2(acc[0][i][0], vi[0], vi[1]); upk2(acc[0][i][1], vi[2], vi[3]);
        upk2(acc[1][i][0], vo[0], vo[1]); upk2(acc[1][i][1], vo[2], vo[3]);
        upk2(acc[2][i][0], vu[0], vu[1]); upk2(acc[2][i][1], vu[2], vu[3]);

        float hv[4], cv[4];
#pragma unroll
        for (int q = 0; q < 4; ++q) {
            const int hc = col + q;
            float I = sigf(vi[q] + bi[hc]);
            float O = sigf(vo[q] + bi[256 + hc]);
            float U = tanh_f(vu[q] + bi[512 + hc]);
            float cc = fmaf(I, U, caA[q]);
            cv[q] = cc;
            hv[q] = O * tanh_f(cc);
        }
        *(float4*)&g_c[grow * 256 + col] = make_float4(cv[0], cv[1], cv[2], cv[3]);
        *(float4*)&g_h[grow * 256 + col] = make_float4(hv[0], hv[1], hv[2], hv[3]);
    }
}

// ---------------------------------------------------------------------------
// fgate_kernel: F0 = sig(h_ch0 @ Uf^T + bf), F1 likewise;
// c_agg = F0*c_ch0 + F1*c_ch1 -> g_ca.  blockIdx.x==0 also emits
// h_tild = h_ch0 + h_ch1 -> g_ht for free during the A-tile loads.
// Same k-major / double-buffered structure as iou_kernel.
// ---------------------------------------------------------------------------
__global__ __launch_bounds__(256)
void fgate_kernel(const float* __restrict__ Uf, const float* __restrict__ bf,
                  int m, int mshift)
{
    __shared__ __align__(16) float As[2][2][16][68];  // [buf][child][k][row]
    __shared__ __align__(16) float Ws[2][16][68];     // [buf][k][col]

    const int tid  = threadIdx.x;
    const int gc0  = blockIdx.x * 64;   // gate-col tile
    const int row0 = blockIdx.y * 64;

    const int arow = tid >> 2;
    const int kq   = (tid & 3) << 2;
    const int rA   = row0 + arow;
    const int bA   = rA >> mshift;
    const int jA   = rA & (m - 1);
    const int ch0  = bA * 511 + (2 * m - 1) + 2 * jA;   // left child row
    const float* ap0 = g_h + ch0 * 256 + kq;            // right child is +256 floats
    float* htp = g_ht + rA * 256 + kq;

    const int nl = tid >> 2;
    const float* wp = Uf + (gc0 + nl) * 256 + kq;
    const bool wr_ht = (blockIdx.x == 0);

    const int tr = tid >> 4;
    const int tc = tid & 15;
    const int rb = tr << 2;
    const int cb = tc << 2;

    u64 acc0[4][2], acc1[4][2];
#pragma unroll
    for (int i = 0; i < 4; ++i) { acc0[i][0] = acc0[i][1] = 0ull; acc1[i][0] = acc1[i][1] = 0ull; }

    // ---- prologue: tile 0
    float4 v0 = *(const float4*)(ap0);
    float4 v1 = *(const float4*)(ap0 + 256);
    float4 wv = *(const float4*)(wp);
    As[0][0][kq + 0][arow] = v0.x; As[0][0][kq + 1][arow] = v0.y;
    As[0][0][kq + 2][arow] = v0.z; As[0][0][kq + 3][arow] = v0.w;
    As[0][1][kq + 0][arow] = v1.x; As[0][1][kq + 1][arow] = v1.y;
    As[0][1][kq + 2][arow] = v1.z; As[0][1][kq + 3][arow] = v1.w;
    Ws[0][kq + 0][nl] = wv.x; Ws[0][kq + 1][nl] = wv.y;
    Ws[0][kq + 2][nl] = wv.z; Ws[0][kq + 3][nl] = wv.w;
    if (wr_ht)
        *(float4*)(htp) = make_float4(v0.x + v1.x, v0.y + v1.y, v0.z + v1.z, v0.w + v1.w);
    __syncthreads();

#pragma unroll 1
    for (int kt = 0; kt < 16; ++kt) {
        const int cur = kt & 1;
        const int nxt = cur ^ 1;
        if (kt < 15) {
            const int k0 = (kt + 1) << 4;
            v0 = *(const float4*)(ap0 + k0);
            v1 = *(const float4*)(ap0 + 256 + k0);
            wv = *(const float4*)(wp + k0);
        }

        const float (*A0b)[68] = As[cur][0];
        const float (*A1b)[68] = As[cur][1];
        const float (*Wsb)[68] = Ws[cur];
#pragma unroll
        for (int kk = 0; kk < 16; ++kk) {
            ulonglong2 w = *(const ulonglong2*)&Wsb[kk][cb];
            float4 a0 = *(const float4*)&A0b[kk][rb];
            float4 a1 = *(const float4*)&A1b[kk][rb];
            u64 q0 = pk2(a0.x, a0.x), q1 = pk2(a0.y, a0.y);
            u64 q2 = pk2(a0.z, a0.z), q3 = pk2(a0.w, a0.w);
            acc0[0][0] = fma2(q0, w.x, acc0[0][0]); acc0[0][1] = fma2(q0, w.y, acc0[0][1]);
            acc0[1][0] = fma2(q1, w.x, acc0[1][0]); acc0[1][1] = fma2(q1, w.y, acc0[1][1]);
            acc0[2][0] = fma2(q2, w.x, acc0[2][0]); acc0[2][1] = fma2(q2, w.y, acc0[2][1]);
            acc0[3][0] = fma2(q3, w.x, acc0[3][0]); acc0[3][1] = fma2(q3, w.y, acc0[3][1]);
            u64 s0 = pk2(a1.x, a1.x), s1 = pk2(a1.y, a1.y);
            u64 s2 = pk2(a1.z, a1.z), s3 = pk2(a1.w, a1.w);
            acc1[0][0] = fma2(s0, w.x, acc1[0][0]); acc1[0][1] = fma2(s0, w.y, acc1[0][1]);
            acc1[1][0] = fma2(s1, w.x, acc1[1][0]); acc1[1][1] = fma2(s1, w.y, acc1[1][1]);
            acc1[2][0] = fma2(s2, w.x, acc1[2][0]); acc1[2][1] = fma2(s2, w.y, acc1[2][1]);
            acc1[3][0] = fma2(s3, w.x, acc1[3][0]); acc1[3][1] = fma2(s3, w.y, acc1[3][1]);
        }

        if (kt < 15) {
            const int k0 = (kt + 1) << 4;
            As[nxt][0][kq + 0][arow] = v0.x; As[nxt][0][kq + 1][arow] = v0.y;
            As[nxt][0][kq + 2][arow] = v0.z; As[nxt][0][kq + 3][arow] = v0.w;
            As[nxt][1][kq + 0][arow] = v1.x; As[nxt][1][kq + 1][arow] = v1.y;
            As[nxt][1][kq + 2][arow] = v1.z; As[nxt][1][kq + 3][arow] = v1.w;
            Ws[nxt][kq + 0][nl] = wv.x; Ws[nxt][kq + 1][nl] = wv.y;
            Ws[nxt][kq + 2][nl] = wv.z; Ws[nxt][kq + 3][nl] = wv.w;
            if (wr_ht)
                *(float4*)(htp + k0) = make_float4(v0.x + v1.x, v0.y + v1.y,
                                                   v0.z + v1.z, v0.w + v1.w);
            __syncthreads();
        }
    }

#pragma unroll
    for (int i = 0; i < 4; ++i) {
        const int r   = row0 + rb + i;
        const int b   = r >> mshift;
        const int j   = r & (m - 1);
        const int c0r = b * 511 + (2 * m - 1) + 2 * j;
        const int gc  = gc0 + cb;

        float4 c0 = *(const float4*)(g_c + c0r * 256 + gc);
        float4 c1 = *(const float4*)(g_c + (c0r + 1) * 256 + gc);
        float c0A[4] = {c0.x, c0.y, c0.z, c0.w};
        float c1A[4] = {c1.x, c1.y, c1.z, c1.w};

        float f0v[4], f1v[4];
        upk2(acc0[i][0], f0v[0], f0v[1]); upk2(acc0[i][1], f0v[2], f0v[3]);
        upk2(acc1[i][0], f1v[0], f1v[1]); upk2(acc1[i][1], f1v[2], f1v[3]);

        float o[4];
#pragma unroll
        for (int q = 0; q < 4; ++q) {
            float bb = bf[gc + q];
            float f0 = sigf(f0v[q] + bb);
            float f1 = sigf(f1v[q] + bb);
            o[q] = f0 * c0A[q] + f1 * c1A[q];
        }
        *(float4*)&g_ca[r * 256 + gc] = make_float4(o[0], o[1], o[2], o[3]);
    }
}

// ---------------------------------------------------------------------------
// build_x2: x2[b] = [ h(node0) | mean over nodes 1..509 of h | emo[b] ]
// ---------------------------------------------------------------------------
__global__ void build_x2(const float* __restrict__ emo)
{
    const int idx = blockIdx.x * 256 + threadIdx.x;
    const int b   = idx / 544;
    const int c2  = idx - b * 544;
    float v;
    if (c2 < 256) {
        v = g_h[b * NNODES * HD + c2];
    } else if (c2 < 512) {
        const int hc = c2 - 256;
        const float* p = g_h + b * NNODES * HD + HD + hc;  // node 1
        float s0 = 0.f, s1 = 0.f, s2 = 0.f, s3 = 0.f;
        int nd = 0;
        for (; nd < 508; nd += 4) {
            s0 += p[(nd + 0) * HD];
            s1 += p[(nd + 1) * HD];
            s2 += p[(nd + 2) * HD];
            s3 += p[(nd + 3) * HD];
        }
        s0 += p[508 * HD];  // node 509
        v = (s0 + s1 + s2 + s3) * (1.0f / 509.0f);
    } else {
        v = emo[b * 32 + (c2 - 512)];
    }
    g_x2[idx] = v;
}

// ---------------------------------------------------------------------------
// mlp_kernel: one block per batch row; 544->128 relu, 128->64 relu, 64->4 sig
// ---------------------------------------------------------------------------
__global__ __launch_bounds__(128)
void mlp_kernel(const float* __restrict__ W_in, const float* __restrict__ b_in,
                const float* __restrict__ W_mid, const float* __restrict__ b_mid,
                const float* __restrict__ W_out, const float* __restrict__ b_out,
                float* __restrict__ out)
{
    __shared__ __align__(16) float xs[544];
    __shared__ __align__(16) float y0[128];
    __shared__ __align__(16) float y1[64];
    const int b = blockIdx.x;
    const int t = threadIdx.x;

    for (int i = t; i < 544; i += 128) xs[i] = g_x2[b * 544 + i];
    __syncthreads();

    {
        float acc = b_in[t];
        const float4* w = (const float4*)(W_in + t * 544);
        const float4* x = (const float4*)xs;
#pragma unroll 8
        for (int q = 0; q < 136; ++q) {
            float4 wv = w[q], xv = x[q];
            acc = fmaf(wv.x, xv.x, acc); acc = fmaf(wv.y, xv.y, acc);
            acc = fmaf(wv.z, xv.z, acc); acc = fmaf(wv.w, xv.w, acc);
        }
        y0[t] = fmaxf(acc, 0.0f);
    }
    __syncthreads();

    if (t < 64) {
        float acc = b_mid[t];
        const float4* w = (const float4*)(W_mid + t * 128);
        const float4* x = (const float4*)y0;
#pragma unroll
        for (int q = 0; q < 32; ++q) {
            float4 wv = w[q], xv = x[q];
            acc = fmaf(wv.x, xv.x, acc); acc = fmaf(wv.y, xv.y, acc);
            acc = fmaf(wv.z, xv.z, acc); acc = fmaf(wv.w, xv.w, acc);
        }
        y1[t] = fmaxf(acc, 0.0f);
    }
    __syncthreads();

    if (t < 4) {
        float acc = b_out[t];
        const float4* w = (const float4*)(W_out + t * 64);
        const float4* x = (const float4*)y1;
#pragma unroll
        for (int q = 0; q < 16; ++q) {
            float4 wv = w[q], xv = x[q];
            acc = fmaf(wv.x, xv.x, acc); acc = fmaf(wv.y, xv.y, acc);
            acc = fmaf(wv.z, xv.z, acc); acc = fmaf(wv.w, xv.w, acc);
        }
        out[b * 4 + t] = sigf(acc);
    }
}

// ---------------------------------------------------------------------------
extern "C" void kernel_launch(void* const* d_in, const int* in_sizes, int n_in,
                              void* d_out, int out_size)
{
    const float* X     = (const float*)d_in[0];
    // d_in[1] = h (zeros, never read by the reference)
    const float* c_in  = (const float*)d_in[2];
    const float* emo   = (const float*)d_in[3];
    const float* W_iou = (const float*)d_in[4];
    const float* U_iou = (const float*)d_in[5];
    const float* b_iou = (const float*)d_in[6];
    const float* U_f_w = (const float*)d_in[7];
    const float* U_f_b = (const float*)d_in[8];
    const float* W_in  = (const float*)d_in[9];
    const float* b_in  = (const float*)d_in[10];
    const float* W_mid = (const float*)d_in[11];
    const float* b_mid = (const float*)d_in[12];
    const float* W_out = (const float*)d_in[13];
    const float* b_out = (const float*)d_in[14];
    float* out = (float*)d_out;

    dim3 blk(256);

    // Leaf level: nodes 255..510, m=256
    iou_kernel<<<dim3(4, (NB * 256) / 64), blk>>>(X, W_iou, b_iou, c_in, 256, 8, 1);

    // Internal levels d = 7 .. 0
    for (int d = 7; d >= 0; --d) {
        int m = 1 << d;
        dim3 grid(4, (NB * m) / 64);
        fgate_kernel<<<grid, blk>>>(U_f_w, U_f_b, m, d);
        iou_kernel<<<grid, blk>>>(X, U_iou, b_iou, c_in, m, d, 0);
    }

    build_x2<<<(NB * 544) / 256, 256>>>(emo);
    mlp_kernel<<<NB, 128>>>(W_in, b_in, W_mid, b_mid, W_out, b_out, out);
}

// round 14
// speedup vs baseline: 1.7721x; 1.7721x over previous
#include <cuda_runtime.h>

typedef unsigned int u32;

#define NB 256

// ---------------- scratch (device globals; no allocation allowed) ----------
__device__ float g_h [NB * 511 * 256];   // h (tf32-rounded) for every node
__device__ float g_c [NB * 511 * 256];   // c (full fp32) for every node
__device__ float g_xr[NB * 256 * 256];   // leaf X slice, tf32-rounded
__device__ float g_wx[768 * 256];        // W_iou tf32-rounded
__device__ float g_wu[768 * 256];        // U_iou tf32-rounded
__device__ float g_wf[256 * 256];        // U_f_w tf32-rounded
__device__ float g_ht[NB * 128 * 256];   // h_tild (tf32-rounded) for current level
__device__ float g_ca[NB * 128 * 256];   // c_agg (fp32) for current level
__device__ float g_x2[NB * 544];

// ---------------- helpers --------------------------------------------------
__device__ __forceinline__ float sigf(float x)   { return 1.0f / (1.0f + __expf(-x)); }
__device__ __forceinline__ float tanh_f(float x) { return 2.0f / (1.0f + __expf(-2.0f * x)) - 1.0f; }
__device__ __forceinline__ float tf32rn(float x) {
    u32 r; asm("cvt.rn.tf32.f32 %0, %1;" : "=r"(r) : "f"(x));
    return __uint_as_float(r);
}
__device__ __forceinline__ u32 smaddr(const void* p) {
    u32 a;
    asm("{ .reg .u64 t; cvta.to.shared.u64 t, %1; cvt.u32.u64 %0, t; }" : "=r"(a) : "l"(p));
    return a;
}

#define CPA(dst, src) asm volatile("cp.async.cg.shared.global [%0], [%1], 16;" :: "r"(dst), "l"(src))
#define CPC()  asm volatile("cp.async.commit_group;" ::: "memory")
#define CPW(n) asm volatile("cp.async.wait_group %0;" :: "n"(n) : "memory")

// m16n8k8 tf32 MMA, D += A*B (D/C aliased)
__device__ __forceinline__ void mma8(float* d, const u32* a, const u32* b) {
    asm volatile("mma.sync.aligned.m16n8k8.row.col.f32.tf32.tf32.f32 "
        "{%0,%1,%2,%3}, {%4,%5,%6,%7}, {%8,%9}, {%0,%1,%2,%3};"
        : "+f"(d[0]), "+f"(d[1]), "+f"(d[2]), "+f"(d[3])
        : "r"(a[0]), "r"(a[1]), "r"(a[2]), "r"(a[3]), "r"(b[0]), "r"(b[1]));
}

// ---------------------------------------------------------------------------
// prep_round: round X-leaf slice + all GEMM weights to tf32 (RN) into scratch.
// ---------------------------------------------------------------------------
__global__ void prep_round(const float* __restrict__ X, const float* __restrict__ Wiou,
                           const float* __restrict__ Uiou, const float* __restrict__ Ufw)
{
    const int X4 = 4194304, W4 = 49152;
    int i = blockIdx.x * 256 + threadIdx.x;   // float4 index
    const float4* src; float* dst;
    if (i < X4) {
        int e = i * 4, b = e >> 16, j = (e >> 8) & 255, k = e & 255;
        src = (const float4*)(X + (b * 511 + 255 + j) * 256 + k);
        dst = g_xr + e;
    } else if (i < X4 + W4) {
        int e = (i - X4) * 4;
        src = (const float4*)(Wiou + e); dst = g_wx + e;
    } else if (i < X4 + 2 * W4) {
        int e = (i - X4 - W4) * 4;
        src = (const float4*)(Uiou + e); dst = g_wu + e;
    } else {
        int e = (i - X4 - 2 * W4) * 4;
        src = (const float4*)(Ufw + e); dst = g_wf + e;
    }
    float4 v = *src;
    v.x = tf32rn(v.x); v.y = tf32rn(v.y); v.z = tf32rn(v.z); v.w = tf32rn(v.w);
    *(float4*)dst = v;
}

// ---------------------------------------------------------------------------
// iou_mma: out = A @ W^T (W 768x256, 3 gates) via mma.sync tf32, fused LSTM
// cell epilogue. Block = 64 rows x 64 cols, 4 warps; warp (rh, chalf) owns a
// 32x32 tile of ALL 3 gates so the epilogue is thread-local.
// Smem chunk (k=32): A 64x32 (8KB) + W 3x64x32 (24KB), double buffered.
// Layout: row-major 32 floats/row, float4 groups XOR-swizzled by (row&3).
// ---------------------------------------------------------------------------
__global__ __launch_bounds__(128, 3)
void iou_mma(const float* __restrict__ bi, const float* __restrict__ Cin,
             int mshift, int leaf)
{
    extern __shared__ float dsm[];   // 2 x 8192 floats
    const int tid = threadIdx.x, wid = tid >> 5, lane = tid & 31;
    const int col0 = blockIdx.x * 64, r0 = blockIdx.y * 64;
    const int rh = wid >> 1, chalf = wid & 1;
    const int g8 = lane >> 2, j = lane & 3, cswz = g8 & 3;
    const u32 smb = smaddr(dsm);

    const float* Asrc = leaf ? g_xr : g_ht;
    const float* Wsrc = leaf ? g_wx : g_wu;

    float acc[3][2][4][4];
#pragma unroll
    for (int g = 0; g < 3; ++g)
#pragma unroll
        for (int mf = 0; mf < 2; ++mf)
#pragma unroll
            for (int nf = 0; nf < 4; ++nf)
#pragma unroll
                for (int e = 0; e < 4; ++e) acc[g][mf][nf][e] = 0.0f;

    auto fill = [&](int c) {
        const u32 base = smb + (c & 1) * 32768;
#pragma unroll
        for (int it = 0; it < 4; ++it) {                 // A: 512 float4
            int i = tid + it * 128, r = i >> 3, q = i & 7;
            CPA(base + r * 128 + ((q ^ (r & 3)) << 4),
                Asrc + (r0 + r) * 256 + c * 32 + q * 4);
        }
#pragma unroll
        for (int it = 0; it < 12; ++it) {                // B: 1536 float4
            int i = tid + it * 128, g = i >> 9, rem = i & 511, n = rem >> 3, q = rem & 7;
            CPA(base + 8192 + g * 8192 + n * 128 + ((q ^ (n & 3)) << 4),
                Wsrc + (g * 256 + col0 + n) * 256 + c * 32 + q * 4);
        }
        CPC();
    };

    fill(0);
    fill(1);

#pragma unroll 1
    for (int c = 0; c < 8; ++c) {
        if (c == 7) { CPW(0); } else { CPW(1); }
        __syncthreads();
        const float* Ab = dsm + (c & 1) * 8192;
        const float* Bb = Ab + 2048;
#pragma unroll
        for (int s = 0; s < 4; ++s) {
            const int p0 = (((2 * s) ^ cswz) << 2) | j;
            const int p1 = (((2 * s + 1) ^ cswz) << 2) | j;
            u32 aa[2][4];
#pragma unroll
            for (int mf = 0; mf < 2; ++mf) {
                const int rr = (rh * 32 + mf * 16 + g8) * 32;
                aa[mf][0] = __float_as_uint(Ab[rr + p0]);
                aa[mf][1] = __float_as_uint(Ab[rr + 256 + p0]);
                aa[mf][2] = __float_as_uint(Ab[rr + p1]);
                aa[mf][3] = __float_as_uint(Ab[rr + 256 + p1]);
            }
#pragma unroll
            for (int g = 0; g < 3; ++g)
#pragma unroll
                for (int nf = 0; nf < 4; ++nf) {
                    const int nn = (g * 64 + chalf * 32 + nf * 8 + g8) * 32;
                    u32 bb[2] = { __float_as_uint(Bb[nn + p0]),
                                  __float_as_uint(Bb[nn + p1]) };
                    mma8(acc[g][0][nf], aa[0], bb);
                    mma8(acc[g][1][nf], aa[1], bb);
                }
        }
        __syncthreads();
        if (c < 6) fill(c + 2);
    }

    // ---- epilogue: gates + cell update + store h,c ----
#pragma unroll
    for (int mf = 0; mf < 2; ++mf)
#pragma unroll
    for (int e = 0; e < 2; ++e) {
        const int r  = r0 + rh * 32 + mf * 16 + g8 + e * 8;
        const int b  = r >> mshift;
        const int jn = r & ((1 << mshift) - 1);
        const int grow = b * 511 + (1 << mshift) - 1 + jn;
        const float* cin = leaf ? (Cin + (long)grow * 256) : (g_ca + (long)r * 256);
#pragma unroll
        for (int nf = 0; nf < 4; ++nf) {
            const int col = col0 + chalf * 32 + nf * 8 + j * 2;
            float2 ci = *(const float2*)(cin + col);
            float cv[2], hv[2];
#pragma unroll
            for (int q = 0; q < 2; ++q) {
                float I = sigf(acc[0][mf][nf][e * 2 + q] + bi[col + q]);
                float O = sigf(acc[1][mf][nf][e * 2 + q] + bi[256 + col + q]);
                float U = tanh_f(acc[2][mf][nf][e * 2 + q] + bi[512 + col + q]);
                float cc = fmaf(I, U, q ? ci.y : ci.x);
                cv[q] = cc;
                hv[q] = tf32rn(O * tanh_f(cc));
            }
            *(float2*)(g_c + (long)grow * 256 + col) = make_float2(cv[0], cv[1]);
            *(float2*)(g_h + (long)grow * 256 + col) = make_float2(hv[0], hv[1]);
        }
    }
}

// ---------------------------------------------------------------------------
// fgate_mma: F0 = sig(ch0@Uf^T + bf), F1 likewise; c_agg = F0*c0 + F1*c1.
// Block = 64 parents x 64 cols, 4 warps; warp (rh, chalf) owns a 32x32 tile
// for BOTH children (epilogue thread-local). blockIdx.x==0 re-reads the
// streamed child h tiles from smem and emits h_tild (tf32-rounded) to g_ht.
// ---------------------------------------------------------------------------
__global__ __launch_bounds__(128, 3)
void fgate_mma(const float* __restrict__ bf, int m, int mshift)
{
    extern __shared__ float dsm[];   // 2 x 6144 floats: A0 2048 | A1 2048 | B 2048
    const int tid = threadIdx.x, wid = tid >> 5, lane = tid & 31;
    const int gc0 = blockIdx.x * 64, r0 = blockIdx.y * 64;
    const int rh = wid >> 1, chalf = wid & 1;
    const int g8 = lane >> 2, j = lane & 3, cswz = g8 & 3;
    const u32 smb = smaddr(dsm);
    const bool wr_ht = (blockIdx.x == 0);

    float acc[2][2][4][4];
#pragma unroll
    for (int ch = 0; ch < 2; ++ch)
#pragma unroll
        for (int mf = 0; mf < 2; ++mf)
#pragma unroll
            for (int nf = 0; nf < 4; ++nf)
#pragma unroll
                for (int e = 0; e < 4; ++e) acc[ch][mf][nf][e] = 0.0f;

    auto fill = [&](int c) {
        const u32 base = smb + (c & 1) * 24576;
#pragma unroll
        for (int it = 0; it < 8; ++it) {                 // A: 1024 float4
            int i = tid + it * 128, ch = i >> 9, rem = i & 511, r = rem >> 3, q = rem & 7;
            int rg = r0 + r;
            int b = rg >> mshift, jn = rg & (m - 1);
            int cg = b * 511 + 2 * m - 1 + 2 * jn + ch;
            CPA(base + ch * 8192 + r * 128 + ((q ^ (r & 3)) << 4),
                g_h + (long)cg * 256 + c * 32 + q * 4);
        }
#pragma unroll
        for (int it = 0; it < 4; ++it) {                 // B: 512 float4
            int i = tid + it * 128, n = i >> 3, q = i & 7;
            CPA(base + 16384 + n * 128 + ((q ^ (n & 3)) << 4),
                g_wf + (gc0 + n) * 256 + c * 32 + q * 4);
        }
        CPC();
    };

    fill(0);
    fill(1);

#pragma unroll 1
    for (int c = 0; c < 8; ++c) {
        if (c == 7) { CPW(0); } else { CPW(1); }
        __syncthreads();
        const float* Ab = dsm + (c & 1) * 6144;
        const float* Bb = Ab + 4096;
#pragma unroll
        for (int s = 0; s < 4; ++s) {
            const int p0 = (((2 * s) ^ cswz) << 2) | j;
            const int p1 = (((2 * s + 1) ^ cswz) << 2) | j;
            u32 aa[2][2][4];
#pragma unroll
            for (int ch = 0; ch < 2; ++ch)
#pragma unroll
                for (int mf = 0; mf < 2; ++mf) {
                    const int rr = ch * 2048 + (rh * 32 + mf * 16 + g8) * 32;
                    aa[ch][mf][0] = __float_as_uint(Ab[rr + p0]);
                    aa[ch][mf][1] = __float_as_uint(Ab[rr + 256 + p0]);
                    aa[ch][mf][2] = __float_as_uint(Ab[rr + p1]);
                    aa[ch][mf][3] = __float_as_uint(Ab[rr + 256 + p1]);
                }
#pragma unroll
            for (int nf = 0; nf < 4; ++nf) {
                const int nn = (chalf * 32 + nf * 8 + g8) * 32;
                u32 bb[2] = { __float_as_uint(Bb[nn + p0]),
                              __float_as_uint(Bb[nn + p1]) };
                mma8(acc[0][0][nf], aa[0][0], bb);
                mma8(acc[0][1][nf], aa[0][1], bb);
                mma8(acc[1][0][nf], aa[1][0], bb);
                mma8(acc[1][1][nf], aa[1][1], bb);
            }
        }
        // h_tild = ch0 + ch1 (tf32-rounded) from the still-valid buffer
        if (wr_ht) {
#pragma unroll
            for (int it = 0; it < 4; ++it) {
                int i = tid + it * 128, r = i >> 3, q = i & 7;
                const float* p0f = Ab + r * 32 + ((q ^ (r & 3)) << 2);
                float4 v0 = *(const float4*)p0f;
                float4 v1 = *(const float4*)(p0f + 2048);
                float4 sv;
                sv.x = tf32rn(v0.x + v1.x); sv.y = tf32rn(v0.y + v1.y);
                sv.z = tf32rn(v0.z + v1.z); sv.w = tf32rn(v0.w + v1.w);
                *(float4*)(g_ht + (long)(r0 + r) * 256 + c * 32 + q * 4) = sv;
            }
        }
        __syncthreads();
        if (c < 6) fill(c + 2);
    }

    // ---- epilogue: f-gates + c_agg ----
#pragma unroll
    for (int mf = 0; mf < 2; ++mf)
#pragma unroll
    for (int e = 0; e < 2; ++e) {
        const int r  = r0 + rh * 32 + mf * 16 + g8 + e * 8;
        const int b  = r >> mshift;
        const int jn = r & (m - 1);
        const int cg = b * 511 + 2 * m - 1 + 2 * jn;
#pragma unroll
        for (int nf = 0; nf < 4; ++nf) {
            const int col = gc0 + chalf * 32 + nf * 8 + j * 2;
            float2 c0v = *(const float2*)(g_c + (long)cg * 256 + col);
            float2 c1v = *(const float2*)(g_c + (long)(cg + 1) * 256 + col);
            float ov[2];
#pragma unroll
            for (int q = 0; q < 2; ++q) {
                float bb = bf[col + q];
                float F0 = sigf(acc[0][mf][nf][e * 2 + q] + bb);
                float F1 = sigf(acc[1][mf][nf][e * 2 + q] + bb);
                ov[q] = F0 * (q ? c0v.y : c0v.x) + F1 * (q ? c1v.y : c1v.x);
            }
            *(float2*)(g_ca + (long)r * 256 + col) = make_float2(ov[0], ov[1]);
        }
    }
}

// ---------------------------------------------------------------------------
// build_x2: x2[b] = [ h(node0) | mean over nodes 1..509 of h | emo[b] ]
// ---------------------------------------------------------------------------
__global__ void build_x2(const float* __restrict__ emo)
{
    const int idx = blockIdx.x * 256 + threadIdx.x;
    const int b   = idx / 544;
    const int c2  = idx - b * 544;
    float v;
    if (c2 < 256) {
        v = g_h[(long)b * 511 * 256 + c2];
    } else if (c2 < 512) {
        const int hc = c2 - 256;
        const float* p = g_h + (long)b * 511 * 256 + 256 + hc;  // node 1
        float s0 = 0.f, s1 = 0.f, s2 = 0.f, s3 = 0.f;
        int nd = 0;
        for (; nd < 508; nd += 4) {
            s0 += p[(nd + 0) * 256];
            s1 += p[(nd + 1) * 256];
            s2 += p[(nd + 2) * 256];
            s3 += p[(nd + 3) * 256];
        }
        s0 += p[508 * 256];  // node 509
        v = (s0 + s1 + s2 + s3) * (1.0f / 509.0f);
    } else {
        v = emo[b * 32 + (c2 - 512)];
    }
    g_x2[idx] = v;
}

// ---------------------------------------------------------------------------
// mlp_kernel: one block per batch row; 544->128 relu, 128->64 relu, 64->4 sig
// ---------------------------------------------------------------------------
__global__ __launch_bounds__(128)
void mlp_kernel(const float* __restrict__ W_in, const float* __restrict__ b_in,
                const float* __restrict__ W_mid, const float* __restrict__ b_mid,
                const float* __restrict__ W_out, const float* __restrict__ b_out,
                float* __restrict__ out)
{
    __shared__ __align__(16) float xs[544];
    __shared__ __align__(16) float y0[128];
    __shared__ __align__(16) float y1[64];
    const int b = blockIdx.x;
    const int t = threadIdx.x;

    for (int i = t; i < 544; i += 128) xs[i] = g_x2[b * 544 + i];
    __syncthreads();

    {
        float acc = b_in[t];
        const float4* w = (const float4*)(W_in + t * 544);
        const float4* x = (const float4*)xs;
#pragma unroll 8
        for (int q = 0; q < 136; ++q) {
            float4 wv = w[q], xv = x[q];
            acc = fmaf(wv.x, xv.x, acc); acc = fmaf(wv.y, xv.y, acc);
            acc = fmaf(wv.z, xv.z, acc); acc = fmaf(wv.w, xv.w, acc);
        }
        y0[t] = fmaxf(acc, 0.0f);
    }
    __syncthreads();

    if (t < 64) {
        float acc = b_mid[t];
        const float4* w = (const float4*)(W_mid + t * 128);
        const float4* x = (const float4*)y0;
#pragma unroll
        for (int q = 0; q < 32; ++q) {
            float4 wv = w[q], xv = x[q];
            acc = fmaf(wv.x, xv.x, acc); acc = fmaf(wv.y, xv.y, acc);
            acc = fmaf(wv.z, xv.z, acc); acc = fmaf(wv.w, xv.w, acc);
        }
        y1[t] = fmaxf(acc, 0.0f);
    }
    __syncthreads();

    if (t < 4) {
        float acc = b_out[t];
        const float4* w = (const float4*)(W_out + t * 64);
        const float4* x = (const float4*)y1;
#pragma unroll
        for (int q = 0; q < 16; ++q) {
            float4 wv = w[q], xv = x[q];
            acc = fmaf(wv.x, xv.x, acc); acc = fmaf(wv.y, xv.y, acc);
            acc = fmaf(wv.z, xv.z, acc); acc = fmaf(wv.w, xv.w, acc);
        }
        out[b * 4 + t] = sigf(acc);
    }
}

// ---------------------------------------------------------------------------
extern "C" void kernel_launch(void* const* d_in, const int* in_sizes, int n_in,
                              void* d_out, int out_size)
{
    const float* X     = (const float*)d_in[0];
    // d_in[1] = h (zeros, never read by the reference)
    const float* c_in  = (const float*)d_in[2];
    const float* emo   = (const float*)d_in[3];
    const float* W_iou = (const float*)d_in[4];
    const float* U_iou = (const float*)d_in[5];
    const float* b_iou = (const float*)d_in[6];
    const float* U_f_w = (const float*)d_in[7];
    const float* U_f_b = (const float*)d_in[8];
    const float* W_in  = (const float*)d_in[9];
    const float* b_in  = (const float*)d_in[10];
    const float* W_mid = (const float*)d_in[11];
    const float* b_mid = (const float*)d_in[12];
    const float* W_out = (const float*)d_in[13];
    const float* b_out = (const float*)d_in[14];
    float* out = (float*)d_out;

    const int IOU_SMEM   = 65536;   // 2 x (8KB A + 24KB B)
    const int FGATE_SMEM = 49152;   // 2 x (16KB A + 8KB B)
    static int s_attr_done = 0;
    if (!s_attr_done) {
        cudaFuncSetAttribute(iou_mma,   cudaFuncAttributeMaxDynamicSharedMemorySize, IOU_SMEM);
        cudaFuncSetAttribute(fgate_mma, cudaFuncAttributeMaxDynamicSharedMemorySize, FGATE_SMEM);
        s_attr_done = 1;
    }

    prep_round<<<16832, 256>>>(X, W_iou, U_iou, U_f_w);

    // Leaf level: 65536 rows (mshift=8)
    iou_mma<<<dim3(4, 1024), 128, IOU_SMEM>>>(b_iou, c_in, 8, 1);

    // Internal levels d = 7 .. 0
    for (int d = 7; d >= 0; --d) {
        int m = 1 << d;
        dim3 grid(4, (NB * m) / 64);
        fgate_mma<<<grid, 128, FGATE_SMEM>>>(U_f_b, m, d);
        iou_mma<<<grid, 128, IOU_SMEM>>>(b_iou, c_in, d, 0);
    }

    build_x2<<<(NB * 544) / 256, 256>>>(emo);
    mlp_kernel<<<NB, 128>>>(W_in, b_in, W_mid, b_mid, W_out, b_out, out);
}